// round 11
// baseline (speedup 1.0000x reference)
#include <cuda_runtime.h>
#include <cstdint>

// Problem dims
#define B_N 64
#define T_T 512
#define V_V 25
#define C_IN 3
#define C_H 64
#define F_F 25
#define G_G 100   // 4*F

// Scratch (device globals; no allocation allowed)
__device__ float g_zx[(size_t)T_T * B_N * V_V * G_G];   // [t][n][v][g]
__device__ float g_hs[(size_t)B_N * T_T * V_V * F_F];   // [n][t][v][f]

__device__ __forceinline__ uint32_t f2tf32(float f) {
    uint32_t u;
    asm("cvt.rna.tf32.f32 %0, %1;" : "=r"(u) : "f"(f));
    return u;
}

__device__ __forceinline__ void mma_tf32(float* d, const uint32_t* a, const uint32_t* b) {
    asm volatile(
        "mma.sync.aligned.m16n8k8.row.col.f32.tf32.tf32.f32 "
        "{%0,%1,%2,%3}, {%4,%5,%6,%7}, {%8,%9}, {%0,%1,%2,%3};\n"
        : "+f"(d[0]), "+f"(d[1]), "+f"(d[2]), "+f"(d[3])
        : "r"(a[0]), "r"(a[1]), "r"(a[2]), "r"(a[3]), "r"(b[0]), "r"(b[1]));
}

__device__ __forceinline__ float hsig(float x) {
    return __saturatef(fmaf(0.2f, x, 0.5f));
}

// ---------------------------------------------------------------------------
// Kernel 1: zx[t,n,v,:] = relu(x[n,t,v,:] @ Wc + bc) @ Wl + bl
// (R1 version, measured 344-346us. UNCHANGED.)
// ---------------------------------------------------------------------------
__global__ __launch_bounds__(128) void k_zx(
    const float* __restrict__ x, const float* __restrict__ Wc,
    const float* __restrict__ bc, const float* __restrict__ Wl,
    const float* __restrict__ bl)
{
    __shared__ float s_B[64 * 104];
    const int tid = threadIdx.x;

    for (int i = tid; i < 64 * 104; i += 128) {
        int k = i / 104, n = i - (i / 104) * 104;
        s_B[i] = (n < G_G) ? Wl[k * G_G + n] : 0.f;
    }
    __syncthreads();

    const int lane = tid & 31, warp = tid >> 5;
    const int gid = lane >> 2;
    const int tig = lane & 3;
    const int rloc0 = warp * 16 + gid;
    const int r0 = blockIdx.x * 64 + rloc0;
    const int r1 = r0 + 8;

    const float x00 = x[r0 * 3 + 0], x01 = x[r0 * 3 + 1], x02 = x[r0 * 3 + 2];
    const float x10 = x[r1 * 3 + 0], x11 = x[r1 * 3 + 1], x12 = x[r1 * 3 + 2];

    float acc[13][4];
#pragma unroll
    for (int i = 0; i < 13; i++) {
#pragma unroll
        for (int j = 0; j < 4; j++) acc[i][j] = 0.f;
    }

#pragma unroll
    for (int kt = 0; kt < 8; kt++) {
        const int c0 = kt * 8 + tig, c1 = c0 + 4;
        float a00 = fmaxf(fmaf(x02, Wc[128 + c0], fmaf(x01, Wc[64 + c0], fmaf(x00, Wc[c0], bc[c0]))), 0.f);
        float a10 = fmaxf(fmaf(x12, Wc[128 + c0], fmaf(x11, Wc[64 + c0], fmaf(x10, Wc[c0], bc[c0]))), 0.f);
        float a01 = fmaxf(fmaf(x02, Wc[128 + c1], fmaf(x01, Wc[64 + c1], fmaf(x00, Wc[c1], bc[c1]))), 0.f);
        float a11 = fmaxf(fmaf(x12, Wc[128 + c1], fmaf(x11, Wc[64 + c1], fmaf(x10, Wc[c1], bc[c1]))), 0.f);

        uint32_t ah[4], al[4];
        ah[0] = f2tf32(a00); al[0] = __float_as_uint(a00 - __uint_as_float(ah[0]));
        ah[1] = f2tf32(a10); al[1] = __float_as_uint(a10 - __uint_as_float(ah[1]));
        ah[2] = f2tf32(a01); al[2] = __float_as_uint(a01 - __uint_as_float(ah[2]));
        ah[3] = f2tf32(a11); al[3] = __float_as_uint(a11 - __uint_as_float(ah[3]));

        const int br0 = (kt * 8 + tig) * 104 + gid;
        const int br1 = (kt * 8 + tig + 4) * 104 + gid;
#pragma unroll
        for (int nt = 0; nt < 13; nt++) {
            float b0f = s_B[br0 + nt * 8];
            float b1f = s_B[br1 + nt * 8];
            uint32_t bh[2], blo[2];
            bh[0] = f2tf32(b0f); blo[0] = __float_as_uint(b0f - __uint_as_float(bh[0]));
            bh[1] = f2tf32(b1f); blo[1] = __float_as_uint(b1f - __uint_as_float(bh[1]));
            mma_tf32(acc[nt], ah, bh);
            mma_tf32(acc[nt], ah, blo);
            mma_tf32(acc[nt], al, bh);
        }
    }

    __syncthreads();
#pragma unroll
    for (int nt = 0; nt < 13; nt++) {
        const int cc = nt * 8 + 2 * tig;
        s_B[rloc0 * 104 + cc]           = acc[nt][0];
        s_B[rloc0 * 104 + cc + 1]       = acc[nt][1];
        s_B[(rloc0 + 8) * 104 + cc]     = acc[nt][2];
        s_B[(rloc0 + 8) * 104 + cc + 1] = acc[nt][3];
    }
    __syncthreads();

    const int pbase = blockIdx.x * 64;
    for (int i = tid; i < 64 * G_G; i += 128) {
        int r = i / G_G, g = i - r * G_G;
        int p = pbase + r;
        int n = p / (T_T * V_V);
        int t = (p / V_V) % T_T;
        int v = p % V_V;
        g_zx[((size_t)(t * B_N + n) * V_V + v) * G_G + g] = s_B[r * 104 + g] + bl[g];
    }
}

// ---------------------------------------------------------------------------
// Kernel 2: LSTM recurrence — WARP PER CELL, barrier-free.
// Lane l (<25) owns LSTM unit l: gates i,f,g,o = indices l, 25+l, 50+l, 75+l.
// U held in 100 registers per lane; h exchanged via __shfl_sync (25/step).
// Gate update needs no cross-lane data. No __syncthreads at all.
// ---------------------------------------------------------------------------
__global__ __launch_bounds__(128) void k_rec(const float* __restrict__ U)
{
    const int lane = threadIdx.x & 31;
    const int cell = blockIdx.x * 4 + (threadIdx.x >> 5);   // 0..1599
    const int n = cell / V_V;
    const int v = cell % V_V;
    const bool act = (lane < F_F);

    // U[j][g]: u0=i-gate col, u1=f, u2=g, u3=o for this lane's unit
    float u0[F_F], u1[F_F], u2[F_F], u3[F_F];
#pragma unroll
    for (int j = 0; j < F_F; j++) {
        const float* Uj = U + j * G_G;
        u0[j] = act ? __ldg(Uj + lane)            : 0.f;
        u1[j] = act ? __ldg(Uj + F_F + lane)      : 0.f;
        u2[j] = act ? __ldg(Uj + 2 * F_F + lane)  : 0.f;
        u3[j] = act ? __ldg(Uj + 3 * F_F + lane)  : 0.f;
    }

    const size_t zstride = (size_t)B_N * V_V * G_G;
    const float* zp = g_zx + (size_t)(n * V_V + v) * G_G;
    float* hp = g_hs + (size_t)n * T_T * V_V * F_F + (size_t)v * F_F;

    float h = 0.f, c = 0.f;
    float z0 = 0.f, z1 = 0.f, z2 = 0.f, z3 = 0.f;
    if (act) {
        z0 = zp[lane];
        z1 = zp[F_F + lane];
        z2 = zp[2 * F_F + lane];
        z3 = zp[3 * F_F + lane];
    }

    for (int t = 0; t < T_T; t++) {
        // prefetch next step's z
        float zn0 = 0.f, zn1 = 0.f, zn2 = 0.f, zn3 = 0.f;
        if (act && t + 1 < T_T) {
            const float* zpn = zp + (size_t)(t + 1) * zstride;
            zn0 = zpn[lane];
            zn1 = zpn[F_F + lane];
            zn2 = zpn[2 * F_F + lane];
            zn3 = zpn[3 * F_F + lane];
        }

        float gi = z0, gf = z1, gg = z2, go = z3;
#pragma unroll
        for (int j = 0; j < F_F; j++) {
            float hj = __shfl_sync(0xffffffffu, h, j);
            gi = fmaf(hj, u0[j], gi);
            gf = fmaf(hj, u1[j], gf);
            gg = fmaf(hj, u2[j], gg);
            go = fmaf(hj, u3[j], go);
        }
        c = hsig(gf) * c + hsig(gi) * tanhf(gg);
        h = hsig(go) * tanhf(c);
        if (act) hp[(size_t)t * (V_V * F_F) + lane] = h;

        z0 = zn0; z1 = zn1; z2 = zn2; z3 = zn3;
    }
}

// ---------------------------------------------------------------------------
// Kernel 3: attention softmax + aggregation, one block per (n,t).
// x1 staged as float4; thread owns (v, c4): per w = 1 broadcast LDS +
// 1 LDS.128 + 4 scalar fmaf -> FMA-bound instead of LDS-bound.
// ---------------------------------------------------------------------------
__global__ __launch_bounds__(256) void k_agg(
    const float* __restrict__ x, const float* __restrict__ Wc,
    const float* __restrict__ bc, const float* __restrict__ bias,
    float* __restrict__ out)
{
    __shared__ float4 s_x14[V_V * 16];   // x1: 25 x 64 as float4
    __shared__ float s_hr[V_V * F_F];
    __shared__ float s_co[V_V * F_F];

    const int b = blockIdx.x;            // n*T + t
    const int tid = threadIdx.x;

    const float* xp = x + (size_t)b * V_V * C_IN;
    float* s_x1 = (float*)s_x14;
    for (int i = tid; i < V_V * C_H; i += 256) {
        int v = i >> 6, cch = i & 63;
        float val = fmaf(xp[v * 3 + 2], Wc[128 + cch],
                    fmaf(xp[v * 3 + 1], Wc[64 + cch],
                    fmaf(xp[v * 3 + 0], Wc[cch], bc[cch])));
        s_x1[i] = fmaxf(val, 0.f);
    }
    const float* hpp = g_hs + (size_t)b * (V_V * F_F);
    for (int i = tid; i < V_V * F_F; i += 256) s_hr[i] = hpp[i];
    __syncthreads();

    if (tid < V_V) {
        const int v = tid;
        float l[F_F];
        float mx = -1e30f;
#pragma unroll
        for (int w = 0; w < F_F; w++) {
            float h = s_hr[v * F_F + w];
            float lv = (h > 0.f ? h : 0.2f * h) + bias[v * V_V + w];
            l[w] = lv;
            mx = fmaxf(mx, lv);
        }
        float s = 0.f;
#pragma unroll
        for (int w = 0; w < F_F; w++) {
            float e = expf(l[w] - mx);
            l[w] = e;
            s += e;
        }
        float inv = 1.f / s;
#pragma unroll
        for (int w = 0; w < F_F; w++) s_co[v * F_F + w] = l[w] * inv;
    }
    __syncthreads();

    float* op = out + (size_t)b * V_V * C_H;
    for (int i = tid; i < V_V * 16; i += 256) {
        int v = i >> 4, c4 = i & 15;
        float a0 = 0.f, a1 = 0.f, a2 = 0.f, a3 = 0.f;
#pragma unroll
        for (int w = 0; w < F_F; w++) {
            float co = s_co[v * F_F + w];       // broadcast within warp
            float4 xv = s_x14[w * 16 + c4];     // LDS.128, 2-way broadcast
            a0 = fmaf(co, xv.x, a0);
            a1 = fmaf(co, xv.y, a1);
            a2 = fmaf(co, xv.z, a2);
            a3 = fmaf(co, xv.w, a3);
        }
        *reinterpret_cast<float4*>(op + v * C_H + c4 * 4) = make_float4(a0, a1, a2, a3);
    }
}

// ---------------------------------------------------------------------------
extern "C" void kernel_launch(void* const* d_in, const int* in_sizes, int n_in,
                              void* d_out, int out_size)
{
    const float* x    = (const float*)d_in[0];   // (64,512,25,3)
    const float* Wc   = (const float*)d_in[1];   // (3,64)
    const float* bc   = (const float*)d_in[2];   // (64,)
    const float* Wl   = (const float*)d_in[3];   // (64,100)
    const float* Ul   = (const float*)d_in[4];   // (25,100)
    const float* bl   = (const float*)d_in[5];   // (100,)
    const float* bias = (const float*)d_in[6];   // (25,25)
    float* out = (float*)d_out;                  // (64,512,25,64)

    k_zx<<<(B_N * T_T * V_V) / 64, 128>>>(x, Wc, bc, Wl, bl);
    k_rec<<<(B_N * V_V) / 4, 128>>>(Ul);
    k_agg<<<B_N * T_T, 256>>>(x, Wc, bc, bias, out);
}